// round 2
// baseline (speedup 1.0000x reference)
#include <cuda_runtime.h>
#include <cstdint>

// Problem constants
#define N_DIM    8192   // K dimension (rows of M, length of D)
#define D_SKETCH 1024   // output rows (length of P)
#define M_COLS   4096   // output cols

// 32 MB scratch for A'[i,k] = w_k * cos(ang(P[i],k)) * D[k]
// (static __device__ global: allowed by the allocation guards)
__device__ float g_A[D_SKETCH * N_DIM];

// ---------------------------------------------------------------------------
// Kernel 1: build A'. Replicates the reference's fp32 rounding EXACTLY:
//   s   = f32( pi / (2*N) )                (double const cast to f32, as jax does)
//   t1  = f32( s * (2*P[i]+1) )            (one fp32 rounding)
//   ang = f32( t1 * k )                    (second fp32 rounding; NO range reduction,
//                                           matching jnp's large-angle fp32 behavior)
//   A'  = cosf(ang) * w_k * D[k]           (D is exactly +-1, so folding it is exact;
//                                           w_k = (k==0 ? 0.5 : 1)/8192, /8192 exact)
// ---------------------------------------------------------------------------
__global__ void build_A_kernel(const float* __restrict__ D,
                               const int*   __restrict__ P) {
    int idx = blockIdx.x * blockDim.x + threadIdx.x;
    if (idx >= D_SKETCH * N_DIM) return;
    int i = idx >> 13;          // / 8192
    int k = idx & (N_DIM - 1);  // % 8192

    const float s = (float)(3.14159265358979323846 / 16384.0);
    int   p   = __ldg(&P[i]);
    float t1  = s * (float)(2 * p + 1);
    float ang = t1 * (float)k;
    float w   = (k == 0 ? 0.5f : 1.0f) * (1.0f / 8192.0f);
    g_A[idx] = cosf(ang) * w * __ldg(&D[k]);
}

// ---------------------------------------------------------------------------
// Kernel 2: fp32 SIMT GEMM  out[1024,4096] = A'[1024,8192] @ M[8192,4096]
// 128x128 CTA tile, BK=8, 256 threads, 8x8 per-thread micro-tile.
// ---------------------------------------------------------------------------
#define BM 128
#define BN 128
#define BK 8
#define TM 8
#define TN 8

__global__ __launch_bounds__(256, 2)
void gemm_kernel(const float* __restrict__ Mmat, float* __restrict__ out) {
    __shared__ float As[BK][BM];   // A tile, transposed on store
    __shared__ float Bs[BK][BN];

    const int bx  = blockIdx.x;           // N (column) tile
    const int by  = blockIdx.y;           // M (d-row) tile
    const int tid = threadIdx.x;
    const int tx  = tid & 15;             // 16 x 16 thread grid
    const int ty  = tid >> 4;

    // A tile load mapping: 128 rows x 8 cols = 256 float4 -> one per thread
    const int a_row = tid >> 1;           // 0..127
    const int a_col = (tid & 1) * 4;      // 0 or 4
    // B tile load mapping: 8 rows x 128 cols = 256 float4 -> one per thread
    const int b_row = tid >> 5;           // 0..7
    const int b_col = (tid & 31) * 4;     // 0..124

    // Hoisted per-thread global pointers (advance by BK each iter)
    const float* ald = g_A  + (size_t)(blockIdx.y * BM + a_row) * N_DIM + a_col;
    const float* bld = Mmat + (size_t)b_row * M_COLS + (size_t)(bx * BN) + b_col;

    float acc[TM][TN];
    #pragma unroll
    for (int i = 0; i < TM; i++)
        #pragma unroll
        for (int j = 0; j < TN; j++) acc[i][j] = 0.0f;

    for (int k0 = 0; k0 < N_DIM; k0 += BK) {
        float4 av = *(const float4*)(ald);
        As[a_col + 0][a_row] = av.x;
        As[a_col + 1][a_row] = av.y;
        As[a_col + 2][a_row] = av.z;
        As[a_col + 3][a_row] = av.w;

        float4 bv = *(const float4*)(bld);
        *(float4*)&Bs[b_row][b_col] = bv;

        ald += BK;
        bld += (size_t)BK * M_COLS;

        __syncthreads();

        #pragma unroll
        for (int kk = 0; kk < BK; kk++) {
            float ra[TM], rb[TN];
            #pragma unroll
            for (int i = 0; i < TM; i++) ra[i] = As[kk][ty * TM + i];
            #pragma unroll
            for (int j = 0; j < TN; j++) rb[j] = Bs[kk][tx * TN + j];
            #pragma unroll
            for (int i = 0; i < TM; i++)
                #pragma unroll
                for (int j = 0; j < TN; j++)
                    acc[i][j] += ra[i] * rb[j];
        }

        __syncthreads();
    }

    const int orow0 = by * BM + ty * TM;
    const int ocol0 = bx * BN + tx * TN;
    #pragma unroll
    for (int i = 0; i < TM; i++) {
        float4* o = (float4*)(out + (size_t)(orow0 + i) * M_COLS + ocol0);
        o[0] = make_float4(acc[i][0], acc[i][1], acc[i][2], acc[i][3]);
        o[1] = make_float4(acc[i][4], acc[i][5], acc[i][6], acc[i][7]);
    }
}

// ---------------------------------------------------------------------------
// kernel_launch: inputs in metadata order: M (f32, 8192*4096), D (f32, 8192),
// P (i32, 1024). Output f32 [1024, 4096] row-major.
// Graph-capturable: two plain kernel launches, no sync, no alloc.
// ---------------------------------------------------------------------------
extern "C" void kernel_launch(void* const* d_in, const int* in_sizes, int n_in,
                              void* d_out, int out_size) {
    const float* Mmat = (const float*)d_in[0];
    const float* D    = (const float*)d_in[1];
    const int*   P    = (const int*)  d_in[2];
    float*       out  = (float*)d_out;

    // Kernel 1: build A' (8.4M elements)
    {
        const int total   = D_SKETCH * N_DIM;
        const int threads = 256;
        const int blocks  = (total + threads - 1) / threads;
        build_A_kernel<<<blocks, threads>>>(D, P);
    }

    // Kernel 2: GEMM
    {
        dim3 grid(M_COLS / BN, D_SKETCH / BM);  // 32 x 8
        gemm_kernel<<<grid, 256>>>(Mmat, out);
    }
}

// round 6
// speedup vs baseline: 2.0608x; 2.0608x over previous
#include <cuda_runtime.h>
#include <cuda_bf16.h>
#include <cstdint>

// Problem constants
#define N_DIM    8192   // K dimension
#define D_SKETCH 1024   // output rows (M of GEMM)
#define M_COLS   4096   // output cols (N of GEMM)

// GEMM tiling
#define BM    128       // CTA M tile
#define BN    128       // CTA N tile
#define KC    32        // K chunk per pipeline stage
#define NITK  (N_DIM / KC)   // 256 k-chunks
#define STAGES 4

// ---------------------------------------------------------------------------
// Static device scratch (allocation-guard-legal)
// ---------------------------------------------------------------------------
__device__ __align__(1024) __nv_bfloat16 g_Ahi[D_SKETCH * N_DIM];  // 16 MB
__device__ __align__(1024) __nv_bfloat16 g_Alo[D_SKETCH * N_DIM];  // 16 MB
__device__ __align__(1024) __nv_bfloat16 g_Bhi[M_COLS * N_DIM];    // 64 MB  [N,K]
__device__ __align__(1024) __nv_bfloat16 g_Blo[M_COLS * N_DIM];    // 64 MB

// ---------------------------------------------------------------------------
// Helpers (all sm_80-era ISA: valid on compute_100)
// ---------------------------------------------------------------------------
__device__ __forceinline__ uint32_t smem_u32(const void* p) {
    uint32_t a;
    asm("{ .reg .u64 t; cvta.to.shared.u64 t, %1; cvt.u32.u64 %0, t; }" : "=r"(a) : "l"(p));
    return a;
}

__device__ __forceinline__ void cpasync16(uint32_t dst, const void* src) {
    asm volatile("cp.async.cg.shared.global [%0], [%1], 16;" :: "r"(dst), "l"(src));
}
#define CP_COMMIT() asm volatile("cp.async.commit_group;" ::: "memory")
#define CP_WAIT2()  asm volatile("cp.async.wait_group 2;" ::: "memory")
#define CP_WAIT0()  asm volatile("cp.async.wait_group 0;" ::: "memory")

__device__ __forceinline__ void ldsm_x4(uint32_t& r0, uint32_t& r1, uint32_t& r2,
                                        uint32_t& r3, uint32_t addr) {
    asm volatile("ldmatrix.sync.aligned.m8n8.x4.shared.b16 {%0,%1,%2,%3}, [%4];"
                 : "=r"(r0), "=r"(r1), "=r"(r2), "=r"(r3) : "r"(addr));
}

__device__ __forceinline__ void mma_bf16(float* d, const uint32_t* a,
                                         uint32_t b0, uint32_t b1) {
    asm volatile(
        "mma.sync.aligned.m16n8k16.row.col.f32.bf16.bf16.f32 "
        "{%0,%1,%2,%3}, {%4,%5,%6,%7}, {%8,%9}, {%0,%1,%2,%3};"
        : "+f"(d[0]), "+f"(d[1]), "+f"(d[2]), "+f"(d[3])
        : "r"(a[0]), "r"(a[1]), "r"(a[2]), "r"(a[3]), "r"(b0), "r"(b1));
}

__device__ __forceinline__ void split_bf16(float a, __nv_bfloat16& hi, __nv_bfloat16& lo) {
    hi = __float2bfloat16(a);                       // RN
    lo = __float2bfloat16(a - __bfloat162float(hi));
}

// ---------------------------------------------------------------------------
// Kernel 1: build A' in bf16 hi/lo. Replicates the reference fp32 rounding:
//   t1 = f32(pi/16384) * f32(2P+1); ang = t1 * f32(k); a = cosf(ang)*w*D[k]
// ---------------------------------------------------------------------------
__global__ void build_A_kernel(const float* __restrict__ D,
                               const int*   __restrict__ P) {
    int idx = blockIdx.x * blockDim.x + threadIdx.x;     // pair index
    int i  = idx >> 12;                                  // 4096 pairs per row
    int kp = (idx & 4095) << 1;

    const float s = (float)(3.14159265358979323846 / 16384.0);
    float t1 = s * (float)(2 * __ldg(&P[i]) + 1);

    __nv_bfloat162 hi2, lo2;
    #pragma unroll
    for (int j = 0; j < 2; j++) {
        int k = kp + j;
        float ang = t1 * (float)k;
        float w   = (k == 0 ? 0.5f : 1.0f) * (1.0f / 8192.0f);
        float a   = cosf(ang) * w * __ldg(&D[k]);
        __nv_bfloat16 hi, lo;
        split_bf16(a, hi, lo);
        if (j == 0) { hi2.x = hi; lo2.x = lo; } else { hi2.y = hi; lo2.y = lo; }
    }
    size_t off = (size_t)i * N_DIM + kp;
    *(__nv_bfloat162*)&g_Ahi[off] = hi2;
    *(__nv_bfloat162*)&g_Alo[off] = lo2;
}

// ---------------------------------------------------------------------------
// Kernel 2: transpose + split M[K=8192, N=4096] -> g_Bhi/g_Blo [N, K]
// ---------------------------------------------------------------------------
__global__ void conv_B_kernel(const float* __restrict__ Mmat) {
    __shared__ float tile[32][33];
    int n0 = blockIdx.x * 32;
    int k0 = blockIdx.y * 32;
    int tx = threadIdx.x, ty = threadIdx.y;   // 32 x 8

    #pragma unroll
    for (int j = 0; j < 4; j++) {
        int k = k0 + ty + j * 8;
        tile[ty + j * 8][tx] = Mmat[(size_t)k * M_COLS + n0 + tx];
    }
    __syncthreads();
    #pragma unroll
    for (int j = 0; j < 4; j++) {
        int n = n0 + ty + j * 8;
        float v = tile[tx][ty + j * 8];
        __nv_bfloat16 hi, lo;
        split_bf16(v, hi, lo);
        size_t off = (size_t)n * N_DIM + k0 + tx;
        g_Bhi[off] = hi;
        g_Blo[off] = lo;
    }
}

// ---------------------------------------------------------------------------
// Kernel 3: mma.sync bf16 GEMM, 128x128 CTA tile, 3-product split accumulation.
//   out = Ahi*Bhi + Ahi*Blo + Alo*Bhi   (fp32 accumulators in registers)
//
// SMEM stage layout: 4 matrices (Ahi, Alo, Bhi, Blo), each 128 rows x 32 bf16,
// row stride 80 bytes (64B data + 16B pad -> ldmatrix bank-conflict-free:
// 8 consecutive rows start at banks {0,20,8,28,16,4,24,12}).
// ---------------------------------------------------------------------------
#define ROWB     80                    // bytes per smem row
#define MAT_SZ   (128 * ROWB)          // 10240 B
#define OFF_AHI  0
#define OFF_ALO  (1 * MAT_SZ)
#define OFF_BHI  (2 * MAT_SZ)
#define OFF_BLO  (3 * MAT_SZ)
#define ST_SIZE  (4 * MAT_SZ)          // 40960 B
#define SMEM_TOTAL (STAGES * ST_SIZE)  // 163840 B

__device__ __forceinline__ void load_stage(uint32_t sstage, int k0,
                                           int aRow0, int nCol0, int tid) {
    // 512 16B-chunks per matrix (128 rows x 4 chunks); 2 chunks/thread/matrix
    #pragma unroll
    for (int h = 0; h < 2; h++) {
        int idx = tid + h * 256;          // 0..511
        int r = idx >> 2, c = idx & 3;
        uint32_t so = (uint32_t)(r * ROWB + c * 16);
        size_t ga = (size_t)(aRow0 + r) * N_DIM + k0 + c * 8;
        size_t gb = (size_t)(nCol0 + r) * N_DIM + k0 + c * 8;
        cpasync16(sstage + OFF_AHI + so, g_Ahi + ga);
        cpasync16(sstage + OFF_ALO + so, g_Alo + ga);
        cpasync16(sstage + OFF_BHI + so, g_Bhi + gb);
        cpasync16(sstage + OFF_BLO + so, g_Blo + gb);
    }
}

__global__ __launch_bounds__(256, 1)
void gemm_mma_kernel(float* __restrict__ out) {
    extern __shared__ __align__(1024) char smem[];
    const uint32_t sbase = smem_u32(smem);
    const int tid  = threadIdx.x;
    const int wid  = tid >> 5;
    const int lane = tid & 31;
    const int wm   = wid >> 2;            // 0..1 -> M offset wm*64
    const int wn   = wid & 3;             // 0..3 -> N offset wn*32
    const int aRow0 = blockIdx.x * BM;    // 8 M tiles
    const int nCol0 = blockIdx.y * BN;    // 32 N tiles

    // ldmatrix per-lane base offsets (within a stage)
    const uint32_t lrow = (lane & 7) + ((lane >> 3) & 1) * 8;  // row within 16
    const uint32_t lcol = ((lane >> 4) & 1) * 16;              // 0 or 16 bytes (k half)
    // A: rows wm*64 + mt*16 + lrow ; B: rows wn*32 + g*16 + lrow
    const uint32_t aoff = (uint32_t)(wm * 64 + lrow) * ROWB + lcol;
    const uint32_t boff = (uint32_t)(wn * 32 + lrow) * ROWB + lcol;

    float acc[4][4][4];
    #pragma unroll
    for (int i = 0; i < 4; i++)
        #pragma unroll
        for (int j = 0; j < 4; j++)
            #pragma unroll
            for (int q = 0; q < 4; q++) acc[i][j][q] = 0.0f;

    // prologue: stages 0..2
    #pragma unroll
    for (int t = 0; t < STAGES - 1; t++) {
        load_stage(sbase + t * ST_SIZE, t * KC, aRow0, nCol0, tid);
        CP_COMMIT();
    }

    for (int t = 0; t < NITK; t++) {
        CP_WAIT2();            // stage t resident (<=2 newer groups pending)
        __syncthreads();       // also protects stage (t-1)%4 from being overwritten

        if (t + STAGES - 1 < NITK) {
            load_stage(sbase + ((t + STAGES - 1) & (STAGES - 1)) * ST_SIZE,
                       (t + STAGES - 1) * KC, aRow0, nCol0, tid);
        }
        CP_COMMIT();           // always commit (empty group in tail keeps count)

        const uint32_t st = sbase + (t & (STAGES - 1)) * ST_SIZE;

        #pragma unroll
        for (int kk = 0; kk < 2; kk++) {   // two k16 steps per chunk
            const uint32_t kb = (uint32_t)(kk * 32);
            uint32_t ah[4][4], al[4][4], bh[2][4], bl[2][4];
            #pragma unroll
            for (int mt = 0; mt < 4; mt++) {
                uint32_t ad = st + aoff + (uint32_t)(mt * 16) * ROWB + kb;
                ldsm_x4(ah[mt][0], ah[mt][1], ah[mt][2], ah[mt][3], ad + OFF_AHI);
                ldsm_x4(al[mt][0], al[mt][1], al[mt][2], al[mt][3], ad + OFF_ALO);
            }
            #pragma unroll
            for (int g = 0; g < 2; g++) {
                uint32_t bd = st + boff + (uint32_t)(g * 16) * ROWB + kb;
                ldsm_x4(bh[g][0], bh[g][1], bh[g][2], bh[g][3], bd + OFF_BHI);
                ldsm_x4(bl[g][0], bl[g][1], bl[g][2], bl[g][3], bd + OFF_BLO);
            }
            // 3 products, 16 tiles each
            #pragma unroll
            for (int mt = 0; mt < 4; mt++) {
                #pragma unroll
                for (int nt = 0; nt < 4; nt++) {
                    const int g = nt >> 1, o = nt & 1;
                    mma_bf16(acc[mt][nt], ah[mt], bh[g][0 + o], bh[g][2 + o]);
                    mma_bf16(acc[mt][nt], ah[mt], bl[g][0 + o], bl[g][2 + o]);
                    mma_bf16(acc[mt][nt], al[mt], bh[g][0 + o], bh[g][2 + o]);
                }
            }
        }
    }

    // epilogue: c fragment -> gmem.  lane l: rows l/4 (+8), cols (l%4)*2 (+1)
    const int r0 = aRow0 + wm * 64 + (lane >> 2);
    const int c0 = nCol0 + wn * 32 + (lane & 3) * 2;
    #pragma unroll
    for (int mt = 0; mt < 4; mt++) {
        #pragma unroll
        for (int nt = 0; nt < 4; nt++) {
            const int rr = r0 + mt * 16;
            const int cc = c0 + nt * 8;
            *(float2*)(out + (size_t)rr * M_COLS + cc) =
                make_float2(acc[mt][nt][0], acc[mt][nt][1]);
            *(float2*)(out + (size_t)(rr + 8) * M_COLS + cc) =
                make_float2(acc[mt][nt][2], acc[mt][nt][3]);
        }
    }
}

// ---------------------------------------------------------------------------
// kernel_launch: M (f32, 8192*4096), D (f32, 8192), P (i32, 1024) ->
// out f32 [1024, 4096]. Graph-capturable: 3 kernel launches, no sync/alloc.
// ---------------------------------------------------------------------------
extern "C" void kernel_launch(void* const* d_in, const int* in_sizes, int n_in,
                              void* d_out, int out_size) {
    const float* Mmat = (const float*)d_in[0];
    const float* D    = (const float*)d_in[1];
    const int*   P    = (const int*)  d_in[2];
    float*       out  = (float*)d_out;

    // Kernel 1: build A' (bf16 hi/lo)
    {
        const int total = D_SKETCH * N_DIM / 2;
        build_A_kernel<<<total / 256, 256>>>(D, P);
    }
    // Kernel 2: transpose + split M
    {
        dim3 grid(M_COLS / 32, N_DIM / 32);   // 128 x 256
        dim3 blk(32, 8);
        conv_B_kernel<<<grid, blk>>>(Mmat);
    }
    // Kernel 3: tensor-core (mma.sync) GEMM. x = M tiles so concurrent CTAs
    // share the L2-resident A and stream B once.
    {
        cudaFuncSetAttribute(gemm_mma_kernel,
                             cudaFuncAttributeMaxDynamicSharedMemorySize, SMEM_TOTAL);
        dim3 grid(D_SKETCH / BM, M_COLS / BN);   // 8 x 32 = 256 CTAs
        gemm_mma_kernel<<<grid, 256, SMEM_TOTAL>>>(out);
    }
}

// round 7
// speedup vs baseline: 2.2524x; 1.0929x over previous
#include <cuda_runtime.h>
#include <cuda_bf16.h>
#include <cstdint>

// Problem constants
#define N_DIM    8192   // K dimension
#define D_SKETCH 1024   // output rows (M of GEMM)
#define M_COLS   4096   // output cols (N of GEMM)

// GEMM tiling
#define BM    128       // CTA M tile
#define BN    256       // CTA N tile
#define KC    32        // K chunk per pipeline stage
#define NITK  (N_DIM / KC)   // 256 k-chunks
#define STAGES 3

// ---------------------------------------------------------------------------
// Static device scratch (allocation-guard-legal)
// ---------------------------------------------------------------------------
__device__ __align__(1024) __nv_bfloat16 g_Ahi[D_SKETCH * N_DIM];  // 16 MB
__device__ __align__(1024) __nv_bfloat16 g_Alo[D_SKETCH * N_DIM];  // 16 MB
__device__ __align__(1024) __nv_bfloat16 g_Bhi[M_COLS * N_DIM];    // 64 MB  [N,K]
__device__ __align__(1024) __nv_bfloat16 g_Blo[M_COLS * N_DIM];    // 64 MB

// ---------------------------------------------------------------------------
// Helpers (all sm_80-era ISA: valid on compute_100)
// ---------------------------------------------------------------------------
__device__ __forceinline__ uint32_t smem_u32(const void* p) {
    uint32_t a;
    asm("{ .reg .u64 t; cvta.to.shared.u64 t, %1; cvt.u32.u64 %0, t; }" : "=r"(a) : "l"(p));
    return a;
}

__device__ __forceinline__ void cpasync16(uint32_t dst, const void* src) {
    asm volatile("cp.async.cg.shared.global [%0], [%1], 16;" :: "r"(dst), "l"(src));
}
#define CP_COMMIT() asm volatile("cp.async.commit_group;" ::: "memory")
#define CP_WAIT1()  asm volatile("cp.async.wait_group 1;" ::: "memory")

__device__ __forceinline__ void ldsm_x4(uint32_t& r0, uint32_t& r1, uint32_t& r2,
                                        uint32_t& r3, uint32_t addr) {
    asm volatile("ldmatrix.sync.aligned.m8n8.x4.shared.b16 {%0,%1,%2,%3}, [%4];"
                 : "=r"(r0), "=r"(r1), "=r"(r2), "=r"(r3) : "r"(addr));
}

__device__ __forceinline__ void mma_bf16(float* d, const uint32_t* a,
                                         uint32_t b0, uint32_t b1) {
    asm volatile(
        "mma.sync.aligned.m16n8k16.row.col.f32.bf16.bf16.f32 "
        "{%0,%1,%2,%3}, {%4,%5,%6,%7}, {%8,%9}, {%0,%1,%2,%3};"
        : "+f"(d[0]), "+f"(d[1]), "+f"(d[2]), "+f"(d[3])
        : "r"(a[0]), "r"(a[1]), "r"(a[2]), "r"(a[3]), "r"(b0), "r"(b1));
}

__device__ __forceinline__ void split_bf16(float a, __nv_bfloat16& hi, __nv_bfloat16& lo) {
    hi = __float2bfloat16(a);                       // RN
    lo = __float2bfloat16(a - __bfloat162float(hi));
}

// ---------------------------------------------------------------------------
// Kernel 1: build A' in bf16 hi/lo. Replicates the reference fp32 rounding:
//   t1 = f32(pi/16384) * f32(2P+1); ang = t1 * f32(k); a = cosf(ang)*w*D[k]
// ---------------------------------------------------------------------------
__global__ void build_A_kernel(const float* __restrict__ D,
                               const int*   __restrict__ P) {
    int idx = blockIdx.x * blockDim.x + threadIdx.x;     // pair index
    int i  = idx >> 12;                                  // 4096 pairs per row
    int kp = (idx & 4095) << 1;

    const float s = (float)(3.14159265358979323846 / 16384.0);
    float t1 = s * (float)(2 * __ldg(&P[i]) + 1);

    __nv_bfloat162 hi2, lo2;
    #pragma unroll
    for (int j = 0; j < 2; j++) {
        int k = kp + j;
        float ang = t1 * (float)k;
        float w   = (k == 0 ? 0.5f : 1.0f) * (1.0f / 8192.0f);
        float a   = cosf(ang) * w * __ldg(&D[k]);
        __nv_bfloat16 hi, lo;
        split_bf16(a, hi, lo);
        if (j == 0) { hi2.x = hi; lo2.x = lo; } else { hi2.y = hi; lo2.y = lo; }
    }
    size_t off = (size_t)i * N_DIM + kp;
    *(__nv_bfloat162*)&g_Ahi[off] = hi2;
    *(__nv_bfloat162*)&g_Alo[off] = lo2;
}

// ---------------------------------------------------------------------------
// Kernel 2: transpose + split M[K=8192, N=4096] -> g_Bhi/g_Blo [N, K]
// ---------------------------------------------------------------------------
__global__ void conv_B_kernel(const float* __restrict__ Mmat) {
    __shared__ float tile[32][33];
    int n0 = blockIdx.x * 32;
    int k0 = blockIdx.y * 32;
    int tx = threadIdx.x, ty = threadIdx.y;   // 32 x 8

    #pragma unroll
    for (int j = 0; j < 4; j++) {
        int k = k0 + ty + j * 8;
        tile[ty + j * 8][tx] = Mmat[(size_t)k * M_COLS + n0 + tx];
    }
    __syncthreads();
    #pragma unroll
    for (int j = 0; j < 4; j++) {
        int n = n0 + ty + j * 8;
        float v = tile[tx][ty + j * 8];
        __nv_bfloat16 hi, lo;
        split_bf16(v, hi, lo);
        size_t off = (size_t)n * N_DIM + k0 + tx;
        g_Bhi[off] = hi;
        g_Blo[off] = lo;
    }
}

// ---------------------------------------------------------------------------
// Kernel 3: mma.sync bf16 GEMM, 128x256 CTA tile, 512 threads, single wave
// (128 CTAs). 3-product split accumulation:
//   out = Ahi*Bhi + Ahi*Blo + Alo*Bhi   (fp32 accumulators in registers)
//
// SMEM stage: Ahi/Alo 128 rows + Bhi/Blo 256 rows, each row 32 bf16, row
// stride 80 B (64 B data + 16 B pad -> ldmatrix conflict-free: 8 consecutive
// rows start at banks {0,20,8,28,16,4,24,12}).
// ---------------------------------------------------------------------------
#define ROWB     80                      // bytes per smem row
#define A_SZ     (128 * ROWB)            // 10240 B
#define B_SZ     (256 * ROWB)            // 20480 B
#define OFF_AHI  0
#define OFF_ALO  (A_SZ)
#define OFF_BHI  (2 * A_SZ)
#define OFF_BLO  (2 * A_SZ + B_SZ)
#define ST_SIZE  (2 * A_SZ + 2 * B_SZ)   // 61440 B
#define SMEM_TOTAL (STAGES * ST_SIZE)    // 184320 B

__device__ __forceinline__ void load_stage(uint32_t sstage, int k0,
                                           int aRow0, int nCol0, int tid) {
    // A: 512 16B-chunks per matrix (128 rows x 4) -> 1 per thread each
    {
        int r = tid >> 2, c = tid & 3;
        uint32_t so = (uint32_t)(r * ROWB + c * 16);
        size_t ga = (size_t)(aRow0 + r) * N_DIM + k0 + c * 8;
        cpasync16(sstage + OFF_AHI + so, g_Ahi + ga);
        cpasync16(sstage + OFF_ALO + so, g_Alo + ga);
    }
    // B: 1024 chunks per matrix (256 rows x 4) -> 2 per thread each
    #pragma unroll
    for (int h = 0; h < 2; h++) {
        int idx = tid + h * 512;
        int r = idx >> 2, c = idx & 3;
        uint32_t so = (uint32_t)(r * ROWB + c * 16);
        size_t gb = (size_t)(nCol0 + r) * N_DIM + k0 + c * 8;
        cpasync16(sstage + OFF_BHI + so, g_Bhi + gb);
        cpasync16(sstage + OFF_BLO + so, g_Blo + gb);
    }
}

__global__ __launch_bounds__(512, 1)
void gemm_mma_kernel(float* __restrict__ out) {
    extern __shared__ __align__(1024) char smem[];
    const uint32_t sbase = smem_u32(smem);
    const int tid  = threadIdx.x;
    const int wid  = tid >> 5;
    const int lane = tid & 31;
    const int wm   = wid & 1;             // 0..1 -> M offset wm*64
    const int wn   = wid >> 1;            // 0..7 -> N offset wn*32
    const int aRow0 = blockIdx.x * BM;    // 8 M tiles
    const int nCol0 = blockIdx.y * BN;    // 16 N tiles

    // ldmatrix per-lane base offsets (within a stage)
    const uint32_t lrow = (lane & 7) + ((lane >> 3) & 1) * 8;  // row within 16
    const uint32_t lcol = ((lane >> 4) & 1) * 16;              // k half (bytes)
    const uint32_t aoff = (uint32_t)(wm * 64 + lrow) * ROWB + lcol;
    const uint32_t boff = (uint32_t)(wn * 32 + lrow) * ROWB + lcol;

    float acc[4][4][4];
    #pragma unroll
    for (int i = 0; i < 4; i++)
        #pragma unroll
        for (int j = 0; j < 4; j++)
            #pragma unroll
            for (int q = 0; q < 4; q++) acc[i][j][q] = 0.0f;

    // prologue: stages 0..1
    #pragma unroll
    for (int t = 0; t < STAGES - 1; t++) {
        load_stage(sbase + t * ST_SIZE, t * KC, aRow0, nCol0, tid);
        CP_COMMIT();
    }

    for (int t = 0; t < NITK; t++) {
        CP_WAIT1();            // stage t resident (<=1 newer group pending)
        __syncthreads();       // all warps done reading stage (t-1)%3

        if (t + STAGES - 1 < NITK) {
            // stage (t+2)%3 == stage (t-1)%3: free after the barrier above
            load_stage(sbase + ((t + STAGES - 1) % STAGES) * ST_SIZE,
                       (t + STAGES - 1) * KC, aRow0, nCol0, tid);
        }
        CP_COMMIT();           // empty group in tail keeps count consistent

        const uint32_t st = sbase + (t % STAGES) * ST_SIZE;

        #pragma unroll
        for (int kk = 0; kk < 2; kk++) {   // two k16 steps per chunk
            const uint32_t kb = (uint32_t)(kk * 32);
            uint32_t bh[2][4], bl[2][4];
            #pragma unroll
            for (int g = 0; g < 2; g++) {
                uint32_t bd = st + boff + (uint32_t)(g * 16) * ROWB + kb;
                ldsm_x4(bh[g][0], bh[g][1], bh[g][2], bh[g][3], bd + OFF_BHI);
                ldsm_x4(bl[g][0], bl[g][1], bl[g][2], bl[g][3], bd + OFF_BLO);
            }
            #pragma unroll
            for (int mt = 0; mt < 4; mt++) {
                const uint32_t ad = st + aoff + (uint32_t)(mt * 16) * ROWB + kb;
                uint32_t af[4];
                ldsm_x4(af[0], af[1], af[2], af[3], ad + OFF_AHI);
                #pragma unroll
                for (int nt = 0; nt < 4; nt++) {
                    const int g = nt >> 1, o = nt & 1;
                    mma_bf16(acc[mt][nt], af, bh[g][0 + o], bh[g][2 + o]);
                }
                #pragma unroll
                for (int nt = 0; nt < 4; nt++) {
                    const int g = nt >> 1, o = nt & 1;
                    mma_bf16(acc[mt][nt], af, bl[g][0 + o], bl[g][2 + o]);
                }
                ldsm_x4(af[0], af[1], af[2], af[3], ad + OFF_ALO);  // reuse
                #pragma unroll
                for (int nt = 0; nt < 4; nt++) {
                    const int g = nt >> 1, o = nt & 1;
                    mma_bf16(acc[mt][nt], af, bh[g][0 + o], bh[g][2 + o]);
                }
            }
        }
    }

    // epilogue: c fragment -> gmem.  lane l: rows l/4 (+8), cols (l%4)*2 (+1)
    const int r0 = aRow0 + wm * 64 + (lane >> 2);
    const int c0 = nCol0 + wn * 32 + (lane & 3) * 2;
    #pragma unroll
    for (int mt = 0; mt < 4; mt++) {
        #pragma unroll
        for (int nt = 0; nt < 4; nt++) {
            const int rr = r0 + mt * 16;
            const int cc = c0 + nt * 8;
            *(float2*)(out + (size_t)rr * M_COLS + cc) =
                make_float2(acc[mt][nt][0], acc[mt][nt][1]);
            *(float2*)(out + (size_t)(rr + 8) * M_COLS + cc) =
                make_float2(acc[mt][nt][2], acc[mt][nt][3]);
        }
    }
}

// ---------------------------------------------------------------------------
// kernel_launch: M (f32, 8192*4096), D (f32, 8192), P (i32, 1024) ->
// out f32 [1024, 4096]. Graph-capturable: 3 kernel launches, no sync/alloc.
// ---------------------------------------------------------------------------
extern "C" void kernel_launch(void* const* d_in, const int* in_sizes, int n_in,
                              void* d_out, int out_size) {
    const float* Mmat = (const float*)d_in[0];
    const float* D    = (const float*)d_in[1];
    const int*   P    = (const int*)  d_in[2];
    float*       out  = (float*)d_out;

    // Kernel 1: build A' (bf16 hi/lo)
    {
        const int total = D_SKETCH * N_DIM / 2;
        build_A_kernel<<<total / 256, 256>>>(D, P);
    }
    // Kernel 2: transpose + split M
    {
        dim3 grid(M_COLS / 32, N_DIM / 32);   // 128 x 256
        dim3 blk(32, 8);
        conv_B_kernel<<<grid, blk>>>(Mmat);
    }
    // Kernel 3: tensor-core (mma.sync) GEMM, 128 CTAs = one full wave.
    {
        cudaFuncSetAttribute(gemm_mma_kernel,
                             cudaFuncAttributeMaxDynamicSharedMemorySize, SMEM_TOTAL);
        dim3 grid(D_SKETCH / BM, M_COLS / BN);   // 8 x 16 = 128 CTAs
        gemm_mma_kernel<<<grid, 512, SMEM_TOTAL>>>(out);
    }
}

// round 9
// speedup vs baseline: 2.4411x; 1.0838x over previous
#include <cuda_runtime.h>
#include <cuda_bf16.h>
#include <cstdint>

// Problem constants
#define N_DIM    8192   // K dimension
#define D_SKETCH 1024   // output rows (M of GEMM)
#define M_COLS   4096   // output cols (N of GEMM)

// GEMM tiling
#define BM    128       // CTA M tile
#define BN    256       // CTA N tile
#define KC    64        // K chunk per pipeline stage
#define NITK  (N_DIM / KC)   // 128 k-chunks
#define STAGES 2

// ---------------------------------------------------------------------------
// Static device scratch (allocation-guard-legal)
// ---------------------------------------------------------------------------
__device__ __align__(1024) __nv_bfloat16 g_Ahi[D_SKETCH * N_DIM];  // 16 MB
__device__ __align__(1024) __nv_bfloat16 g_Alo[D_SKETCH * N_DIM];  // 16 MB
__device__ __align__(1024) __nv_bfloat16 g_Bhi[M_COLS * N_DIM];    // 64 MB  [N,K]
__device__ __align__(1024) __nv_bfloat16 g_Blo[M_COLS * N_DIM];    // 64 MB

// ---------------------------------------------------------------------------
// Helpers (all sm_80-era ISA: valid on compute_100)
// ---------------------------------------------------------------------------
__device__ __forceinline__ uint32_t smem_u32(const void* p) {
    uint32_t a;
    asm("{ .reg .u64 t; cvta.to.shared.u64 t, %1; cvt.u32.u64 %0, t; }" : "=r"(a) : "l"(p));
    return a;
}

__device__ __forceinline__ void cpasync16(uint32_t dst, const void* src) {
    asm volatile("cp.async.cg.shared.global [%0], [%1], 16;" :: "r"(dst), "l"(src));
}
#define CP_COMMIT() asm volatile("cp.async.commit_group;" ::: "memory")
#define CP_WAIT0()  asm volatile("cp.async.wait_group 0;" ::: "memory")

__device__ __forceinline__ void ldsm_x4(uint32_t& r0, uint32_t& r1, uint32_t& r2,
                                        uint32_t& r3, uint32_t addr) {
    asm volatile("ldmatrix.sync.aligned.m8n8.x4.shared.b16 {%0,%1,%2,%3}, [%4];"
                 : "=r"(r0), "=r"(r1), "=r"(r2), "=r"(r3) : "r"(addr));
}

__device__ __forceinline__ void mma_bf16(float* d, const uint32_t* a,
                                         uint32_t b0, uint32_t b1) {
    asm volatile(
        "mma.sync.aligned.m16n8k16.row.col.f32.bf16.bf16.f32 "
        "{%0,%1,%2,%3}, {%4,%5,%6,%7}, {%8,%9}, {%0,%1,%2,%3};"
        : "+f"(d[0]), "+f"(d[1]), "+f"(d[2]), "+f"(d[3])
        : "r"(a[0]), "r"(a[1]), "r"(a[2]), "r"(a[3]), "r"(b0), "r"(b1));
}

__device__ __forceinline__ void split_bf16(float a, __nv_bfloat16& hi, __nv_bfloat16& lo) {
    hi = __float2bfloat16(a);                       // RN
    lo = __float2bfloat16(a - __bfloat162float(hi));
}

// ---------------------------------------------------------------------------
// Kernel 1: build A' in bf16 hi/lo. Replicates the reference fp32 rounding:
//   t1 = f32(pi/16384) * f32(2P+1); ang = t1 * f32(k); a = cosf(ang)*w*D[k]
// ---------------------------------------------------------------------------
__global__ void build_A_kernel(const float* __restrict__ D,
                               const int*   __restrict__ P) {
    int idx = blockIdx.x * blockDim.x + threadIdx.x;     // pair index
    int i  = idx >> 12;                                  // 4096 pairs per row
    int kp = (idx & 4095) << 1;

    const float s = (float)(3.14159265358979323846 / 16384.0);
    float t1 = s * (float)(2 * __ldg(&P[i]) + 1);

    __nv_bfloat162 hi2, lo2;
    #pragma unroll
    for (int j = 0; j < 2; j++) {
        int k = kp + j;
        float ang = t1 * (float)k;
        float w   = (k == 0 ? 0.5f : 1.0f) * (1.0f / 8192.0f);
        float a   = cosf(ang) * w * __ldg(&D[k]);
        __nv_bfloat16 hi, lo;
        split_bf16(a, hi, lo);
        if (j == 0) { hi2.x = hi; lo2.x = lo; } else { hi2.y = hi; lo2.y = lo; }
    }
    size_t off = (size_t)i * N_DIM + kp;
    *(__nv_bfloat162*)&g_Ahi[off] = hi2;
    *(__nv_bfloat162*)&g_Alo[off] = lo2;
}

// ---------------------------------------------------------------------------
// Kernel 2: transpose + split M[K=8192, N=4096] -> g_Bhi/g_Blo [N, K]
// 64k x 32n tiles, bf16x2 vectorized stores.
// ---------------------------------------------------------------------------
__global__ void conv_B_kernel(const float* __restrict__ Mmat) {
    __shared__ float tile[64][33];
    int n0 = blockIdx.x * 32;
    int k0 = blockIdx.y * 64;
    int tx = threadIdx.x, ty = threadIdx.y;   // 32 x 8

    #pragma unroll
    for (int j = 0; j < 8; j++) {
        int kk = ty + j * 8;                  // 0..63
        tile[kk][tx] = Mmat[(size_t)(k0 + kk) * M_COLS + n0 + tx];
    }
    __syncthreads();
    #pragma unroll
    for (int j = 0; j < 4; j++) {
        int nn = ty + j * 8;                  // 0..31
        float v0 = tile[tx * 2 + 0][nn];
        float v1 = tile[tx * 2 + 1][nn];
        __nv_bfloat16 h0, l0, h1, l1;
        split_bf16(v0, h0, l0);
        split_bf16(v1, h1, l1);
        __nv_bfloat162 h2, l2;
        h2.x = h0; h2.y = h1; l2.x = l0; l2.y = l1;
        size_t off = (size_t)(n0 + nn) * N_DIM + k0 + tx * 2;
        *(__nv_bfloat162*)&g_Bhi[off] = h2;
        *(__nv_bfloat162*)&g_Blo[off] = l2;
    }
}

// ---------------------------------------------------------------------------
// Kernel 3: mma.sync bf16 GEMM, 128x256 CTA tile, 512 threads, single wave
// (128 CTAs). 3-product split accumulation:
//   out = Ahi*Bhi + Ahi*Blo + Alo*Bhi   (fp32 accumulators in registers)
//
// SMEM stage: rows of 64 bf16 (128 B data) + 16 B pad -> ROWB=144.
// ldmatrix conflict-free: 8 consecutive rows start at word-banks
// {0,4,8,12,16,20,24,28}+const; each 16B segment spans 4 disjoint banks.
// 2-stage double buffer: WAIT0 -> barrier -> prefetch next -> compute.
// ---------------------------------------------------------------------------
#define ROWB     144                     // bytes per smem row
#define OFF_AHI  0
#define OFF_ALO  (128 * ROWB)            // 18432
#define OFF_BHI  (2 * 128 * ROWB)        // 36864
#define OFF_BLO  (2 * 128 * ROWB + 256 * ROWB)   // 73728
#define ST_SIZE  (2 * 128 * ROWB + 2 * 256 * ROWB) // 110592
#define SMEM_TOTAL (STAGES * ST_SIZE)    // 221184

__device__ __forceinline__ void load_stage(uint32_t sstage, int k0,
                                           int aRow0, int nCol0, int tid) {
    // A matrices: 128 rows x 8 16B-chunks = 1024 chunks each; 2/thread each
    #pragma unroll
    for (int h = 0; h < 2; h++) {
        int idx = tid + h * 512;
        int r = idx >> 3, c = idx & 7;
        uint32_t so = (uint32_t)(r * ROWB + c * 16);
        size_t ga = (size_t)(aRow0 + r) * N_DIM + k0 + c * 8;
        cpasync16(sstage + OFF_AHI + so, g_Ahi + ga);
        cpasync16(sstage + OFF_ALO + so, g_Alo + ga);
    }
    // B matrices: 256 rows x 8 chunks = 2048 chunks each; 4/thread each
    #pragma unroll
    for (int h = 0; h < 4; h++) {
        int idx = tid + h * 512;
        int r = idx >> 3, c = idx & 7;
        uint32_t so = (uint32_t)(r * ROWB + c * 16);
        size_t gb = (size_t)(nCol0 + r) * N_DIM + k0 + c * 8;
        cpasync16(sstage + OFF_BHI + so, g_Bhi + gb);
        cpasync16(sstage + OFF_BLO + so, g_Blo + gb);
    }
}

__global__ __launch_bounds__(512, 1)
void gemm_mma_kernel(float* __restrict__ out) {
    extern __shared__ __align__(1024) char smem[];
    const uint32_t sbase = smem_u32(smem);
    const int tid  = threadIdx.x;
    const int wid  = tid >> 5;
    const int lane = tid & 31;
    const int wm   = wid & 1;             // 0..1 -> M offset wm*64
    const int wn   = wid >> 1;            // 0..7 -> N offset wn*32
    const int aRow0 = blockIdx.x * BM;    // 8 M tiles
    const int nCol0 = blockIdx.y * BN;    // 16 N tiles

    // ldmatrix per-lane base offsets (within a stage)
    const uint32_t lrow = (lane & 7) + ((lane >> 3) & 1) * 8;  // row within 16
    const uint32_t lcol = ((lane >> 4) & 1) * 16;              // k half (bytes)
    const uint32_t aoff = (uint32_t)(wm * 64 + lrow) * ROWB + lcol;
    const uint32_t boff = (uint32_t)(wn * 32 + lrow) * ROWB + lcol;

    float acc[4][4][4];
    #pragma unroll
    for (int i = 0; i < 4; i++)
        #pragma unroll
        for (int j = 0; j < 4; j++)
            #pragma unroll
            for (int q = 0; q < 4; q++) acc[i][j][q] = 0.0f;

    // prologue: stage 0
    load_stage(sbase, 0, aRow0, nCol0, tid);
    CP_COMMIT();

    for (int t = 0; t < NITK; t++) {
        CP_WAIT0();            // own cp.async for stage t complete
        __syncthreads();       // data visible; prev compute done (buffer free)

        if (t + 1 < NITK) {    // prefetch overlaps the whole compute below
            load_stage(sbase + ((t + 1) & 1) * ST_SIZE, (t + 1) * KC,
                       aRow0, nCol0, tid);
            CP_COMMIT();
        }

        const uint32_t st = sbase + (t & 1) * ST_SIZE;

        #pragma unroll
        for (int kk = 0; kk < 4; kk++) {   // four k16 steps per chunk
            const uint32_t kb = (uint32_t)(kk * 32);
            uint32_t bh[2][4], bl[2][4];
            #pragma unroll
            for (int g = 0; g < 2; g++) {
                uint32_t bd = st + boff + (uint32_t)(g * 16) * ROWB + kb;
                ldsm_x4(bh[g][0], bh[g][1], bh[g][2], bh[g][3], bd + OFF_BHI);
                ldsm_x4(bl[g][0], bl[g][1], bl[g][2], bl[g][3], bd + OFF_BLO);
            }
            #pragma unroll
            for (int mt = 0; mt < 4; mt++) {
                const uint32_t ad = st + aoff + (uint32_t)(mt * 16) * ROWB + kb;
                uint32_t af[4];
                ldsm_x4(af[0], af[1], af[2], af[3], ad + OFF_AHI);
                #pragma unroll
                for (int nt = 0; nt < 4; nt++) {
                    const int g = nt >> 1, o = nt & 1;
                    mma_bf16(acc[mt][nt], af, bh[g][0 + o], bh[g][2 + o]);
                }
                #pragma unroll
                for (int nt = 0; nt < 4; nt++) {
                    const int g = nt >> 1, o = nt & 1;
                    mma_bf16(acc[mt][nt], af, bl[g][0 + o], bl[g][2 + o]);
                }
                ldsm_x4(af[0], af[1], af[2], af[3], ad + OFF_ALO);  // reuse
                #pragma unroll
                for (int nt = 0; nt < 4; nt++) {
                    const int g = nt >> 1, o = nt & 1;
                    mma_bf16(acc[mt][nt], af, bh[g][0 + o], bh[g][2 + o]);
                }
            }
        }
    }

    // epilogue: c fragment -> gmem.  lane l: rows l/4 (+8), cols (l%4)*2 (+1)
    const int r0 = aRow0 + wm * 64 + (lane >> 2);
    const int c0 = nCol0 + wn * 32 + (lane & 3) * 2;
    #pragma unroll
    for (int mt = 0; mt < 4; mt++) {
        #pragma unroll
        for (int nt = 0; nt < 4; nt++) {
            const int rr = r0 + mt * 16;
            const int cc = c0 + nt * 8;
            *(float2*)(out + (size_t)rr * M_COLS + cc) =
                make_float2(acc[mt][nt][0], acc[mt][nt][1]);
            *(float2*)(out + (size_t)(rr + 8) * M_COLS + cc) =
                make_float2(acc[mt][nt][2], acc[mt][nt][3]);
        }
    }
}

// ---------------------------------------------------------------------------
// kernel_launch: M (f32, 8192*4096), D (f32, 8192), P (i32, 1024) ->
// out f32 [1024, 4096]. Graph-capturable: 3 kernel launches, no sync/alloc.
// ---------------------------------------------------------------------------
extern "C" void kernel_launch(void* const* d_in, const int* in_sizes, int n_in,
                              void* d_out, int out_size) {
    const float* Mmat = (const float*)d_in[0];
    const float* D    = (const float*)d_in[1];
    const int*   P    = (const int*)  d_in[2];
    float*       out  = (float*)d_out;

    // Kernel 1: build A' (bf16 hi/lo)
    {
        const int total = D_SKETCH * N_DIM / 2;
        build_A_kernel<<<total / 256, 256>>>(D, P);
    }
    // Kernel 2: transpose + split M
    {
        dim3 grid(M_COLS / 32, N_DIM / 64);   // 128 x 128
        dim3 blk(32, 8);
        conv_B_kernel<<<grid, blk>>>(Mmat);
    }
    // Kernel 3: tensor-core (mma.sync) GEMM, 128 CTAs = one full wave.
    {
        cudaFuncSetAttribute(gemm_mma_kernel,
                             cudaFuncAttributeMaxDynamicSharedMemorySize, SMEM_TOTAL);
        dim3 grid(D_SKETCH / BM, M_COLS / BN);   // 8 x 16 = 128 CTAs
        gemm_mma_kernel<<<grid, 512, SMEM_TOTAL>>>(out);
    }
}

// round 10
// speedup vs baseline: 2.4809x; 1.0163x over previous
#include <cuda_runtime.h>
#include <cuda_bf16.h>
#include <cstdint>

// Problem constants
#define N_DIM    8192   // K dimension
#define D_SKETCH 1024   // output rows (M of GEMM)
#define M_COLS   4096   // output cols (N of GEMM)

// GEMM tiling
#define BM    128       // CTA M tile
#define BN    256       // CTA N tile
#define KC    64        // K chunk per pipeline stage
#define NITK  (N_DIM / KC)   // 128 k-chunks
#define STAGES 2

// ---------------------------------------------------------------------------
// Static device scratch (allocation-guard-legal)
// ---------------------------------------------------------------------------
__device__ __align__(1024) __nv_bfloat16 g_Ahi[D_SKETCH * N_DIM];  // 16 MB
__device__ __align__(1024) __nv_bfloat16 g_Alo[D_SKETCH * N_DIM];  // 16 MB
__device__ __align__(1024) __nv_bfloat16 g_Bhi[M_COLS * N_DIM];    // 64 MB  [N,K]
__device__ __align__(1024) __nv_bfloat16 g_Blo[M_COLS * N_DIM];    // 64 MB

// ---------------------------------------------------------------------------
// Helpers (all sm_80-era ISA: valid on compute_100)
// ---------------------------------------------------------------------------
__device__ __forceinline__ uint32_t smem_u32(const void* p) {
    uint32_t a;
    asm("{ .reg .u64 t; cvta.to.shared.u64 t, %1; cvt.u32.u64 %0, t; }" : "=r"(a) : "l"(p));
    return a;
}

__device__ __forceinline__ void cpasync16(uint32_t dst, const void* src) {
    asm volatile("cp.async.cg.shared.global [%0], [%1], 16;" :: "r"(dst), "l"(src));
}
#define CP_COMMIT() asm volatile("cp.async.commit_group;" ::: "memory")
#define CP_WAIT0()  asm volatile("cp.async.wait_group 0;" ::: "memory")

__device__ __forceinline__ void ldsm_x4(uint32_t& r0, uint32_t& r1, uint32_t& r2,
                                        uint32_t& r3, uint32_t addr) {
    asm volatile("ldmatrix.sync.aligned.m8n8.x4.shared.b16 {%0,%1,%2,%3}, [%4];"
                 : "=r"(r0), "=r"(r1), "=r"(r2), "=r"(r3) : "r"(addr));
}

__device__ __forceinline__ void mma_bf16(float* d, const uint32_t* a,
                                         uint32_t b0, uint32_t b1) {
    asm volatile(
        "mma.sync.aligned.m16n8k16.row.col.f32.bf16.bf16.f32 "
        "{%0,%1,%2,%3}, {%4,%5,%6,%7}, {%8,%9}, {%0,%1,%2,%3};"
        : "+f"(d[0]), "+f"(d[1]), "+f"(d[2]), "+f"(d[3])
        : "r"(a[0]), "r"(a[1]), "r"(a[2]), "r"(a[3]), "r"(b0), "r"(b1));
}

__device__ __forceinline__ void split_bf16(float a, __nv_bfloat16& hi, __nv_bfloat16& lo) {
    hi = __float2bfloat16(a);                       // RN
    lo = __float2bfloat16(a - __bfloat162float(hi));
}

// ---------------------------------------------------------------------------
// Kernel 1: build A' in bf16 hi/lo. Replicates the reference fp32 rounding:
//   t1 = f32(pi/16384) * f32(2P+1); ang = t1 * f32(k); a = cosf(ang)*w*D[k]
// ---------------------------------------------------------------------------
__global__ void build_A_kernel(const float* __restrict__ D,
                               const int*   __restrict__ P) {
    int idx = blockIdx.x * blockDim.x + threadIdx.x;     // pair index
    int i  = idx >> 12;                                  // 4096 pairs per row
    int kp = (idx & 4095) << 1;

    const float s = (float)(3.14159265358979323846 / 16384.0);
    float t1 = s * (float)(2 * __ldg(&P[i]) + 1);

    __nv_bfloat162 hi2, lo2;
    #pragma unroll
    for (int j = 0; j < 2; j++) {
        int k = kp + j;
        float ang = t1 * (float)k;
        float w   = (k == 0 ? 0.5f : 1.0f) * (1.0f / 8192.0f);
        float a   = cosf(ang) * w * __ldg(&D[k]);
        __nv_bfloat16 hi, lo;
        split_bf16(a, hi, lo);
        if (j == 0) { hi2.x = hi; lo2.x = lo; } else { hi2.y = hi; lo2.y = lo; }
    }
    size_t off = (size_t)i * N_DIM + kp;
    *(__nv_bfloat162*)&g_Ahi[off] = hi2;
    *(__nv_bfloat162*)&g_Alo[off] = lo2;
}

// ---------------------------------------------------------------------------
// Kernel 2: transpose + split M[K=8192, N=4096] -> g_Bhi/g_Blo [N, K]
// 64k x 32n tiles, bf16x2 vectorized stores.
// ---------------------------------------------------------------------------
__global__ void conv_B_kernel(const float* __restrict__ Mmat) {
    __shared__ float tile[64][33];
    int n0 = blockIdx.x * 32;
    int k0 = blockIdx.y * 64;
    int tx = threadIdx.x, ty = threadIdx.y;   // 32 x 8

    #pragma unroll
    for (int j = 0; j < 8; j++) {
        int kk = ty + j * 8;                  // 0..63
        tile[kk][tx] = Mmat[(size_t)(k0 + kk) * M_COLS + n0 + tx];
    }
    __syncthreads();
    #pragma unroll
    for (int j = 0; j < 4; j++) {
        int nn = ty + j * 8;                  // 0..31
        float v0 = tile[tx * 2 + 0][nn];
        float v1 = tile[tx * 2 + 1][nn];
        __nv_bfloat16 h0, l0, h1, l1;
        split_bf16(v0, h0, l0);
        split_bf16(v1, h1, l1);
        __nv_bfloat162 h2, l2;
        h2.x = h0; h2.y = h1; l2.x = l0; l2.y = l1;
        size_t off = (size_t)(n0 + nn) * N_DIM + k0 + tx * 2;
        *(__nv_bfloat162*)&g_Bhi[off] = h2;
        *(__nv_bfloat162*)&g_Blo[off] = l2;
    }
}

// ---------------------------------------------------------------------------
// Kernel 3: mma.sync bf16 GEMM, 128x256 CTA tile, 256 threads (8 warps,
// 64x64 warp tiles -> minimal smem re-reads), single wave (128 CTAs).
// 3-product split accumulation:
//   out = Ahi*Bhi + Ahi*Blo + Alo*Bhi   (fp32 accumulators in registers)
//
// SMEM stage: rows of 64 bf16 (128 B data) + 16 B pad -> ROWB=144.
// ldmatrix conflict-free: 8 consecutive rows start at word-banks
// {0,4,8,12,16,20,24,28}+const; each 16B segment spans 4 disjoint banks.
// 2-stage double buffer: WAIT0 -> barrier -> prefetch next -> compute.
// ---------------------------------------------------------------------------
#define ROWB     144                     // bytes per smem row
#define OFF_AHI  0
#define OFF_ALO  (128 * ROWB)            // 18432
#define OFF_BHI  (2 * 128 * ROWB)        // 36864
#define OFF_BLO  (2 * 128 * ROWB + 256 * ROWB)   // 73728
#define ST_SIZE  (2 * 128 * ROWB + 2 * 256 * ROWB) // 110592
#define SMEM_TOTAL (STAGES * ST_SIZE)    // 221184

__device__ __forceinline__ void load_stage(uint32_t sstage, int k0,
                                           int aRow0, int nCol0, int tid) {
    // A matrices: 128 rows x 8 16B-chunks = 1024 chunks each; 4/thread each
    #pragma unroll
    for (int h = 0; h < 4; h++) {
        int idx = tid + h * 256;
        int r = idx >> 3, c = idx & 7;
        uint32_t so = (uint32_t)(r * ROWB + c * 16);
        size_t ga = (size_t)(aRow0 + r) * N_DIM + k0 + c * 8;
        cpasync16(sstage + OFF_AHI + so, g_Ahi + ga);
        cpasync16(sstage + OFF_ALO + so, g_Alo + ga);
    }
    // B matrices: 256 rows x 8 chunks = 2048 chunks each; 8/thread each
    #pragma unroll
    for (int h = 0; h < 8; h++) {
        int idx = tid + h * 256;
        int r = idx >> 3, c = idx & 7;
        uint32_t so = (uint32_t)(r * ROWB + c * 16);
        size_t gb = (size_t)(nCol0 + r) * N_DIM + k0 + c * 8;
        cpasync16(sstage + OFF_BHI + so, g_Bhi + gb);
        cpasync16(sstage + OFF_BLO + so, g_Blo + gb);
    }
}

__global__ __launch_bounds__(256, 1)
void gemm_mma_kernel(float* __restrict__ out) {
    extern __shared__ __align__(1024) char smem[];
    const uint32_t sbase = smem_u32(smem);
    const int tid  = threadIdx.x;
    const int wid  = tid >> 5;
    const int lane = tid & 31;
    const int wm   = wid & 1;             // 0..1 -> M offset wm*64
    const int wn   = wid >> 1;            // 0..3 -> N offset wn*64
    const int aRow0 = blockIdx.x * BM;    // 8 M tiles
    const int nCol0 = blockIdx.y * BN;    // 16 N tiles

    // ldmatrix per-lane base offsets (within a stage)
    const uint32_t lrow = (lane & 7) + ((lane >> 3) & 1) * 8;  // row within 16
    const uint32_t lcol = ((lane >> 4) & 1) * 16;              // k half (bytes)
    const uint32_t aoff = (uint32_t)(wm * 64 + lrow) * ROWB + lcol;
    const uint32_t boff = (uint32_t)(wn * 64 + lrow) * ROWB + lcol;

    float acc[4][8][4];                   // 128 regs: 64 rows x 64 cols / warp
    #pragma unroll
    for (int i = 0; i < 4; i++)
        #pragma unroll
        for (int j = 0; j < 8; j++)
            #pragma unroll
            for (int q = 0; q < 4; q++) acc[i][j][q] = 0.0f;

    // prologue: stage 0
    load_stage(sbase, 0, aRow0, nCol0, tid);
    CP_COMMIT();

    for (int t = 0; t < NITK; t++) {
        CP_WAIT0();            // own cp.async for stage t complete
        __syncthreads();       // data visible; prev compute done (buffer free)

        if (t + 1 < NITK) {    // prefetch overlaps the whole compute below
            load_stage(sbase + ((t + 1) & 1) * ST_SIZE, (t + 1) * KC,
                       aRow0, nCol0, tid);
            CP_COMMIT();
        }

        const uint32_t st = sbase + (t & 1) * ST_SIZE;

        #pragma unroll
        for (int kk = 0; kk < 4; kk++) {   // four k16 steps per chunk
            const uint32_t kb = (uint32_t)(kk * 32);
            uint32_t bh[4][4], bl[4][4];
            #pragma unroll
            for (int g = 0; g < 4; g++) {  // 4 n16 groups (64 cols)
                uint32_t bd = st + boff + (uint32_t)(g * 16) * ROWB + kb;
                ldsm_x4(bh[g][0], bh[g][1], bh[g][2], bh[g][3], bd + OFF_BHI);
                ldsm_x4(bl[g][0], bl[g][1], bl[g][2], bl[g][3], bd + OFF_BLO);
            }
            #pragma unroll
            for (int mt = 0; mt < 4; mt++) {
                const uint32_t ad = st + aoff + (uint32_t)(mt * 16) * ROWB + kb;
                uint32_t af[4];
                ldsm_x4(af[0], af[1], af[2], af[3], ad + OFF_AHI);
                #pragma unroll
                for (int nt = 0; nt < 8; nt++) {
                    const int g = nt >> 1, o = nt & 1;
                    mma_bf16(acc[mt][nt], af, bh[g][0 + o], bh[g][2 + o]);
                }
                #pragma unroll
                for (int nt = 0; nt < 8; nt++) {
                    const int g = nt >> 1, o = nt & 1;
                    mma_bf16(acc[mt][nt], af, bl[g][0 + o], bl[g][2 + o]);
                }
                ldsm_x4(af[0], af[1], af[2], af[3], ad + OFF_ALO);  // reuse
                #pragma unroll
                for (int nt = 0; nt < 8; nt++) {
                    const int g = nt >> 1, o = nt & 1;
                    mma_bf16(acc[mt][nt], af, bh[g][0 + o], bh[g][2 + o]);
                }
            }
        }
    }

    // epilogue: c fragment -> gmem.  lane l: rows l/4 (+8), cols (l%4)*2 (+1)
    const int r0 = aRow0 + wm * 64 + (lane >> 2);
    const int c0 = nCol0 + wn * 64 + (lane & 3) * 2;
    #pragma unroll
    for (int mt = 0; mt < 4; mt++) {
        #pragma unroll
        for (int nt = 0; nt < 8; nt++) {
            const int rr = r0 + mt * 16;
            const int cc = c0 + nt * 8;
            *(float2*)(out + (size_t)rr * M_COLS + cc) =
                make_float2(acc[mt][nt][0], acc[mt][nt][1]);
            *(float2*)(out + (size_t)(rr + 8) * M_COLS + cc) =
                make_float2(acc[mt][nt][2], acc[mt][nt][3]);
        }
    }
}

// ---------------------------------------------------------------------------
// kernel_launch: M (f32, 8192*4096), D (f32, 8192), P (i32, 1024) ->
// out f32 [1024, 4096]. Graph-capturable: 3 kernel launches, no sync/alloc.
// ---------------------------------------------------------------------------
extern "C" void kernel_launch(void* const* d_in, const int* in_sizes, int n_in,
                              void* d_out, int out_size) {
    const float* Mmat = (const float*)d_in[0];
    const float* D    = (const float*)d_in[1];
    const int*   P    = (const int*)  d_in[2];
    float*       out  = (float*)d_out;

    // Kernel 1: build A' (bf16 hi/lo)
    {
        const int total = D_SKETCH * N_DIM / 2;
        build_A_kernel<<<total / 256, 256>>>(D, P);
    }
    // Kernel 2: transpose + split M
    {
        dim3 grid(M_COLS / 32, N_DIM / 64);   // 128 x 128
        dim3 blk(32, 8);
        conv_B_kernel<<<grid, blk>>>(Mmat);
    }
    // Kernel 3: tensor-core (mma.sync) GEMM, 128 CTAs = one full wave.
    {
        cudaFuncSetAttribute(gemm_mma_kernel,
                             cudaFuncAttributeMaxDynamicSharedMemorySize, SMEM_TOTAL);
        dim3 grid(D_SKETCH / BM, M_COLS / BN);   // 8 x 16 = 128 CTAs
        gemm_mma_kernel<<<grid, 256, SMEM_TOTAL>>>(out);
    }
}

// round 13
// speedup vs baseline: 3.5634x; 1.4363x over previous
#include <cuda_runtime.h>
#include <cuda_fp16.h>
#include <cstdint>

// Problem constants
#define N_DIM    8192   // K dimension
#define D_SKETCH 1024   // output rows (M of GEMM)
#define M_COLS   4096   // output cols (N of GEMM)

// GEMM tiling
#define BM    128       // CTA M tile
#define BN    256       // CTA N tile
#define KC    64        // K chunk per pipeline stage
#define NITK  (N_DIM / KC)   // 128 k-chunks
#define STAGES 2

// ---------------------------------------------------------------------------
// Static device scratch (allocation-guard-legal)
// A is pre-scaled by 8192 (exact power of two, undone in the GEMM epilogue):
//   a' = cos(ang) * (k==0 ? 0.5 : 1) * D[k]   in [-1, 1]
// Split A into fp16 hi/lo (~22 effective mantissa bits -> A essentially exact).
// B stays a single fp16 matrix (its 2^-11 quantization dominates the error).
// ---------------------------------------------------------------------------
__device__ __align__(1024) __half g_Ahi[D_SKETCH * N_DIM];  // 16 MB
__device__ __align__(1024) __half g_Alo[D_SKETCH * N_DIM];  // 16 MB
__device__ __align__(1024) __half g_Bh [M_COLS * N_DIM];    // 64 MB  [N,K]

// ---------------------------------------------------------------------------
// Helpers (all sm_80-era ISA: valid on compute_100)
// ---------------------------------------------------------------------------
__device__ __forceinline__ uint32_t smem_u32(const void* p) {
    uint32_t a;
    asm("{ .reg .u64 t; cvta.to.shared.u64 t, %1; cvt.u32.u64 %0, t; }" : "=r"(a) : "l"(p));
    return a;
}

__device__ __forceinline__ void cpasync16(uint32_t dst, const void* src) {
    asm volatile("cp.async.cg.shared.global [%0], [%1], 16;" :: "r"(dst), "l"(src));
}
#define CP_COMMIT() asm volatile("cp.async.commit_group;" ::: "memory")
#define CP_WAIT0()  asm volatile("cp.async.wait_group 0;" ::: "memory")

__device__ __forceinline__ void ldsm_x4(uint32_t& r0, uint32_t& r1, uint32_t& r2,
                                        uint32_t& r3, uint32_t addr) {
    asm volatile("ldmatrix.sync.aligned.m8n8.x4.shared.b16 {%0,%1,%2,%3}, [%4];"
                 : "=r"(r0), "=r"(r1), "=r"(r2), "=r"(r3) : "r"(addr));
}

__device__ __forceinline__ void mma_f16(float* d, const uint32_t* a,
                                        uint32_t b0, uint32_t b1) {
    asm volatile(
        "mma.sync.aligned.m16n8k16.row.col.f32.f16.f16.f32 "
        "{%0,%1,%2,%3}, {%4,%5,%6,%7}, {%8,%9}, {%0,%1,%2,%3};"
        : "+f"(d[0]), "+f"(d[1]), "+f"(d[2]), "+f"(d[3])
        : "r"(a[0]), "r"(a[1]), "r"(a[2]), "r"(a[3]), "r"(b0), "r"(b1));
}

__device__ __forceinline__ void split_f16(float a, __half& hi, __half& lo) {
    hi = __float2half_rn(a);
    lo = __float2half_rn(a - __half2float(hi));
}

// ---------------------------------------------------------------------------
// Kernel 1: build A' in fp16 hi/lo. Replicates the reference fp32 rounding:
//   t1 = f32(pi/16384) * f32(2P+1); ang = t1 * f32(k)
//   a' = cosf(ang) * (k==0?0.5:1) * D[k]        (pre-scaled by 8192)
// ---------------------------------------------------------------------------
__global__ void build_A_kernel(const float* __restrict__ D,
                               const int*   __restrict__ P) {
    int idx = blockIdx.x * blockDim.x + threadIdx.x;     // pair index
    int i  = idx >> 12;                                  // 4096 pairs per row
    int kp = (idx & 4095) << 1;

    const float s = (float)(3.14159265358979323846 / 16384.0);
    float t1 = s * (float)(2 * __ldg(&P[i]) + 1);

    __half2 hi2, lo2;
    #pragma unroll
    for (int j = 0; j < 2; j++) {
        int k = kp + j;
        float ang = t1 * (float)k;
        float w   = (k == 0 ? 0.5f : 1.0f);              // 1/8192 applied in epilogue
        float a   = cosf(ang) * w * __ldg(&D[k]);
        __half hi, lo;
        split_f16(a, hi, lo);
        if (j == 0) { hi2.x = hi; lo2.x = lo; } else { hi2.y = hi; lo2.y = lo; }
    }
    size_t off = (size_t)i * N_DIM + kp;
    *(__half2*)&g_Ahi[off] = hi2;
    *(__half2*)&g_Alo[off] = lo2;
}

// ---------------------------------------------------------------------------
// Kernel 2: transpose M[K=8192, N=4096] -> g_Bh [N, K] (single fp16)
// 64k x 32n tiles, half2 vectorized stores.
// ---------------------------------------------------------------------------
__global__ void conv_B_kernel(const float* __restrict__ Mmat) {
    __shared__ float tile[64][33];
    int n0 = blockIdx.x * 32;
    int k0 = blockIdx.y * 64;
    int tx = threadIdx.x, ty = threadIdx.y;   // 32 x 8

    #pragma unroll
    for (int j = 0; j < 8; j++) {
        int kk = ty + j * 8;                  // 0..63
        tile[kk][tx] = Mmat[(size_t)(k0 + kk) * M_COLS + n0 + tx];
    }
    __syncthreads();
    #pragma unroll
    for (int j = 0; j < 4; j++) {
        int nn = ty + j * 8;                  // 0..31
        __half2 h2;
        h2.x = __float2half_rn(tile[tx * 2 + 0][nn]);
        h2.y = __float2half_rn(tile[tx * 2 + 1][nn]);
        size_t off = (size_t)(n0 + nn) * N_DIM + k0 + tx * 2;
        *(__half2*)&g_Bh[off] = h2;
    }
}

// ---------------------------------------------------------------------------
// Kernel 3: mma.sync fp16 GEMM, 128x256 CTA tile, 256 threads (8 warps,
// 64x64 warp tiles), single wave (128 CTAs). 2-product split accumulation:
//   out = (Ahi*B + Alo*B) * (1/8192)    (fp32 accumulators in registers)
//
// SMEM stage: rows of 64 fp16 (128 B data) + 16 B pad -> ROWB=144.
// ldmatrix conflict-free: 8 consecutive rows start at word-banks
// {0,4,8,12,16,20,24,28}+const; each 16B segment spans 4 disjoint banks.
// 2-stage double buffer: WAIT0 -> barrier -> prefetch next -> compute.
// ---------------------------------------------------------------------------
#define ROWB     144                     // bytes per smem row
#define OFF_AHI  0
#define OFF_ALO  (128 * ROWB)            // 18432
#define OFF_BH   (2 * 128 * ROWB)        // 36864
#define ST_SIZE  (2 * 128 * ROWB + 256 * ROWB)   // 73728
#define SMEM_TOTAL (STAGES * ST_SIZE)    // 147456

__device__ __forceinline__ void load_stage(uint32_t sstage, int k0,
                                           int aRow0, int nCol0, int tid) {
    // A matrices: 128 rows x 8 16B-chunks = 1024 chunks each; 4/thread each
    #pragma unroll
    for (int h = 0; h < 4; h++) {
        int idx = tid + h * 256;
        int r = idx >> 3, c = idx & 7;
        uint32_t so = (uint32_t)(r * ROWB + c * 16);
        size_t ga = (size_t)(aRow0 + r) * N_DIM + k0 + c * 8;
        cpasync16(sstage + OFF_AHI + so, g_Ahi + ga);
        cpasync16(sstage + OFF_ALO + so, g_Alo + ga);
    }
    // B matrix: 256 rows x 8 chunks = 2048 chunks; 8/thread
    #pragma unroll
    for (int h = 0; h < 8; h++) {
        int idx = tid + h * 256;
        int r = idx >> 3, c = idx & 7;
        uint32_t so = (uint32_t)(r * ROWB + c * 16);
        size_t gb = (size_t)(nCol0 + r) * N_DIM + k0 + c * 8;
        cpasync16(sstage + OFF_BH + so, g_Bh + gb);
    }
}

__global__ __launch_bounds__(256, 1)
void gemm_mma_kernel(float* __restrict__ out) {
    extern __shared__ __align__(1024) char smem[];
    const uint32_t sbase = smem_u32(smem);
    const int tid  = threadIdx.x;
    const int wid  = tid >> 5;
    const int lane = tid & 31;
    const int wm   = wid & 1;             // 0..1 -> M offset wm*64
    const int wn   = wid >> 1;            // 0..3 -> N offset wn*64
    const int aRow0 = blockIdx.x * BM;    // 8 M tiles
    const int nCol0 = blockIdx.y * BN;    // 16 N tiles

    // ldmatrix per-lane base offsets (within a stage)
    const uint32_t lrow = (lane & 7) + ((lane >> 3) & 1) * 8;  // row within 16
    const uint32_t lcol = ((lane >> 4) & 1) * 16;              // k half (bytes)
    const uint32_t aoff = (uint32_t)(wm * 64 + lrow) * ROWB + lcol;
    const uint32_t boff = (uint32_t)(wn * 64 + lrow) * ROWB + lcol;

    float acc[4][8][4];                   // 128 regs: 64 rows x 64 cols / warp
    #pragma unroll
    for (int i = 0; i < 4; i++)
        #pragma unroll
        for (int j = 0; j < 8; j++)
            #pragma unroll
            for (int q = 0; q < 4; q++) acc[i][j][q] = 0.0f;

    // prologue: stage 0
    load_stage(sbase, 0, aRow0, nCol0, tid);
    CP_COMMIT();

    for (int t = 0; t < NITK; t++) {
        CP_WAIT0();            // own cp.async for stage t complete
        __syncthreads();       // data visible; prev compute done (buffer free)

        if (t + 1 < NITK) {    // prefetch overlaps the whole compute below
            load_stage(sbase + ((t + 1) & 1) * ST_SIZE, (t + 1) * KC,
                       aRow0, nCol0, tid);
            CP_COMMIT();
        }

        const uint32_t st = sbase + (t & 1) * ST_SIZE;

        #pragma unroll
        for (int kk = 0; kk < 4; kk++) {   // four k16 steps per chunk
            const uint32_t kb = (uint32_t)(kk * 32);
            uint32_t bh[4][4];
            #pragma unroll
            for (int g = 0; g < 4; g++) {  // 4 n16 groups (64 cols)
                uint32_t bd = st + boff + (uint32_t)(g * 16) * ROWB + kb;
                ldsm_x4(bh[g][0], bh[g][1], bh[g][2], bh[g][3], bd + OFF_BH);
            }
            #pragma unroll
            for (int mt = 0; mt < 4; mt++) {
                const uint32_t ad = st + aoff + (uint32_t)(mt * 16) * ROWB + kb;
                uint32_t af[4];
                ldsm_x4(af[0], af[1], af[2], af[3], ad + OFF_AHI);
                #pragma unroll
                for (int nt = 0; nt < 8; nt++) {
                    const int g = nt >> 1, o = nt & 1;
                    mma_f16(acc[mt][nt], af, bh[g][0 + o], bh[g][2 + o]);
                }
                ldsm_x4(af[0], af[1], af[2], af[3], ad + OFF_ALO);  // reuse
                #pragma unroll
                for (int nt = 0; nt < 8; nt++) {
                    const int g = nt >> 1, o = nt & 1;
                    mma_f16(acc[mt][nt], af, bh[g][0 + o], bh[g][2 + o]);
                }
            }
        }
    }

    // epilogue: undo the x8192 A pre-scale (exact), c fragment -> gmem.
    const float inv = 1.0f / 8192.0f;
    const int r0 = aRow0 + wm * 64 + (lane >> 2);
    const int c0 = nCol0 + wn * 64 + (lane & 3) * 2;
    #pragma unroll
    for (int mt = 0; mt < 4; mt++) {
        #pragma unroll
        for (int nt = 0; nt < 8; nt++) {
            const int rr = r0 + mt * 16;
            const int cc = c0 + nt * 8;
            *(float2*)(out + (size_t)rr * M_COLS + cc) =
                make_float2(acc[mt][nt][0] * inv, acc[mt][nt][1] * inv);
            *(float2*)(out + (size_t)(rr + 8) * M_COLS + cc) =
                make_float2(acc[mt][nt][2] * inv, acc[mt][nt][3] * inv);
        }
    }
}

// ---------------------------------------------------------------------------
// kernel_launch: M (f32, 8192*4096), D (f32, 8192), P (i32, 1024) ->
// out f32 [1024, 4096]. Graph-capturable: 3 kernel launches, no sync/alloc.
// ---------------------------------------------------------------------------
extern "C" void kernel_launch(void* const* d_in, const int* in_sizes, int n_in,
                              void* d_out, int out_size) {
    const float* Mmat = (const float*)d_in[0];
    const float* D    = (const float*)d_in[1];
    const int*   P    = (const int*)  d_in[2];
    float*       out  = (float*)d_out;

    // Kernel 1: build A' (fp16 hi/lo, pre-scaled by 8192)
    {
        const int total = D_SKETCH * N_DIM / 2;
        build_A_kernel<<<total / 256, 256>>>(D, P);
    }
    // Kernel 2: transpose M -> fp16 [N,K]
    {
        dim3 grid(M_COLS / 32, N_DIM / 64);   // 128 x 128
        dim3 blk(32, 8);
        conv_B_kernel<<<grid, blk>>>(Mmat);
    }
    // Kernel 3: tensor-core (mma.sync fp16) GEMM, 128 CTAs = one full wave.
    {
        cudaFuncSetAttribute(gemm_mma_kernel,
                             cudaFuncAttributeMaxDynamicSharedMemorySize, SMEM_TOTAL);
        dim3 grid(D_SKETCH / BM, M_COLS / BN);   // 8 x 16 = 128 CTAs
        gemm_mma_kernel<<<grid, 256, SMEM_TOTAL>>>(out);
    }
}

// round 16
// speedup vs baseline: 5.9305x; 1.6643x over previous
#include <cuda_runtime.h>
#include <cuda_fp16.h>
#include <cstdint>

// Problem constants
#define N_DIM    8192   // K dimension
#define D_SKETCH 1024   // output rows (M of GEMM)
#define M_COLS   4096   // output cols (N of GEMM)

// GEMM tiling
#define BM    128       // CTA M tile
#define BN    256       // CTA N tile
#define KC    64        // K chunk per pipeline stage
#define NITK  (N_DIM / KC)   // 128 k-chunks
#define STAGES 2

// ---------------------------------------------------------------------------
// Static device scratch (allocation-guard-legal)
// A is pre-scaled by 8192 (exact power of two, undone in the GEMM epilogue):
//   a' = cos(ang) * (k==0 ? 0.5 : 1) * D[k]   in [-1, 1],  stored as fp16.
// B is a single fp16 matrix. Both contribute ~2^-11/sqrt(3) RMS relative
// error; measured total predicted ~3e-4 vs threshold 1e-3.
// ---------------------------------------------------------------------------
__device__ __align__(1024) __half g_Ah[D_SKETCH * N_DIM];  // 16 MB
__device__ __align__(1024) __half g_Bh[M_COLS * N_DIM];    // 64 MB  [N,K]

// ---------------------------------------------------------------------------
// Helpers (all sm_80-era ISA: valid on compute_100)
// ---------------------------------------------------------------------------
__device__ __forceinline__ uint32_t smem_u32(const void* p) {
    uint32_t a;
    asm("{ .reg .u64 t; cvta.to.shared.u64 t, %1; cvt.u32.u64 %0, t; }" : "=r"(a) : "l"(p));
    return a;
}

__device__ __forceinline__ void cpasync16(uint32_t dst, const void* src) {
    asm volatile("cp.async.cg.shared.global [%0], [%1], 16;" :: "r"(dst), "l"(src));
}
#define CP_COMMIT() asm volatile("cp.async.commit_group;" ::: "memory")
#define CP_WAIT0()  asm volatile("cp.async.wait_group 0;" ::: "memory")

__device__ __forceinline__ void ldsm_x4(uint32_t& r0, uint32_t& r1, uint32_t& r2,
                                        uint32_t& r3, uint32_t addr) {
    asm volatile("ldmatrix.sync.aligned.m8n8.x4.shared.b16 {%0,%1,%2,%3}, [%4];"
                 : "=r"(r0), "=r"(r1), "=r"(r2), "=r"(r3) : "r"(addr));
}

__device__ __forceinline__ void mma_f16(float* d, const uint32_t* a,
                                        uint32_t b0, uint32_t b1) {
    asm volatile(
        "mma.sync.aligned.m16n8k16.row.col.f32.f16.f16.f32 "
        "{%0,%1,%2,%3}, {%4,%5,%6,%7}, {%8,%9}, {%0,%1,%2,%3};"
        : "+f"(d[0]), "+f"(d[1]), "+f"(d[2]), "+f"(d[3])
        : "r"(a[0]), "r"(a[1]), "r"(a[2]), "r"(a[3]), "r"(b0), "r"(b1));
}

// ---------------------------------------------------------------------------
// Kernel 1: build A' in fp16. Replicates the reference fp32 rounding:
//   t1 = f32(pi/16384) * f32(2P+1); ang = t1 * f32(k)
//   a' = cosf(ang) * (k==0?0.5:1) * D[k]        (pre-scaled by 8192)
// ---------------------------------------------------------------------------
__global__ void build_A_kernel(const float* __restrict__ D,
                               const int*   __restrict__ P) {
    int idx = blockIdx.x * blockDim.x + threadIdx.x;     // pair index
    int i  = idx >> 12;                                  // 4096 pairs per row
    int kp = (idx & 4095) << 1;

    const float s = (float)(3.14159265358979323846 / 16384.0);
    float t1 = s * (float)(2 * __ldg(&P[i]) + 1);

    __half2 h2;
    #pragma unroll
    for (int j = 0; j < 2; j++) {
        int k = kp + j;
        float ang = t1 * (float)k;
        float w   = (k == 0 ? 0.5f : 1.0f);              // 1/8192 applied in epilogue
        float a   = cosf(ang) * w * __ldg(&D[k]);
        if (j == 0) h2.x = __float2half_rn(a); else h2.y = __float2half_rn(a);
    }
    *(__half2*)&g_Ah[(size_t)i * N_DIM + kp] = h2;
}

// ---------------------------------------------------------------------------
// Kernel 2: transpose M[K=8192, N=4096] -> g_Bh [N, K] (single fp16)
// 64k x 32n tiles, half2 vectorized stores.
// ---------------------------------------------------------------------------
__global__ void conv_B_kernel(const float* __restrict__ Mmat) {
    __shared__ float tile[64][33];
    int n0 = blockIdx.x * 32;
    int k0 = blockIdx.y * 64;
    int tx = threadIdx.x, ty = threadIdx.y;   // 32 x 8

    #pragma unroll
    for (int j = 0; j < 8; j++) {
        int kk = ty + j * 8;                  // 0..63
        tile[kk][tx] = Mmat[(size_t)(k0 + kk) * M_COLS + n0 + tx];
    }
    __syncthreads();
    #pragma unroll
    for (int j = 0; j < 4; j++) {
        int nn = ty + j * 8;                  // 0..31
        __half2 h2;
        h2.x = __float2half_rn(tile[tx * 2 + 0][nn]);
        h2.y = __float2half_rn(tile[tx * 2 + 1][nn]);
        size_t off = (size_t)(n0 + nn) * N_DIM + k0 + tx * 2;
        *(__half2*)&g_Bh[off] = h2;
    }
}

// ---------------------------------------------------------------------------
// Kernel 3: mma.sync fp16 GEMM, 128x256 CTA tile, 256 threads (8 warps,
// 64x64 warp tiles), single wave (128 CTAs). Single product:
//   out = (A*B) * (1/8192)    (fp32 accumulators in registers)
//
// SMEM stage: rows of 64 fp16 (128 B data) + 16 B pad -> ROWB=144.
// ldmatrix conflict-free: 8 consecutive rows start at word-banks
// {0,4,8,12,16,20,24,28}+const; each 16B segment spans 4 disjoint banks.
// 2-stage double buffer: WAIT0 -> barrier -> prefetch next -> compute.
// ---------------------------------------------------------------------------
#define ROWB     144                     // bytes per smem row
#define OFF_AH   0
#define OFF_BH   (128 * ROWB)            // 18432
#define ST_SIZE  (128 * ROWB + 256 * ROWB)   // 55296
#define SMEM_TOTAL (STAGES * ST_SIZE)    // 110592

__device__ __forceinline__ void load_stage(uint32_t sstage, int k0,
                                           int aRow0, int nCol0, int tid) {
    // A: 128 rows x 8 16B-chunks = 1024 chunks; 4/thread
    #pragma unroll
    for (int h = 0; h < 4; h++) {
        int idx = tid + h * 256;
        int r = idx >> 3, c = idx & 7;
        uint32_t so = (uint32_t)(r * ROWB + c * 16);
        size_t ga = (size_t)(aRow0 + r) * N_DIM + k0 + c * 8;
        cpasync16(sstage + OFF_AH + so, g_Ah + ga);
    }
    // B: 256 rows x 8 chunks = 2048 chunks; 8/thread
    #pragma unroll
    for (int h = 0; h < 8; h++) {
        int idx = tid + h * 256;
        int r = idx >> 3, c = idx & 7;
        uint32_t so = (uint32_t)(r * ROWB + c * 16);
        size_t gb = (size_t)(nCol0 + r) * N_DIM + k0 + c * 8;
        cpasync16(sstage + OFF_BH + so, g_Bh + gb);
    }
}

__global__ __launch_bounds__(256, 1)
void gemm_mma_kernel(float* __restrict__ out) {
    extern __shared__ __align__(1024) char smem[];
    const uint32_t sbase = smem_u32(smem);
    const int tid  = threadIdx.x;
    const int wid  = tid >> 5;
    const int lane = tid & 31;
    const int wm   = wid & 1;             // 0..1 -> M offset wm*64
    const int wn   = wid >> 1;            // 0..3 -> N offset wn*64
    const int aRow0 = blockIdx.x * BM;    // 8 M tiles
    const int nCol0 = blockIdx.y * BN;    // 16 N tiles

    // ldmatrix per-lane base offsets (within a stage)
    const uint32_t lrow = (lane & 7) + ((lane >> 3) & 1) * 8;  // row within 16
    const uint32_t lcol = ((lane >> 4) & 1) * 16;              // k half (bytes)
    const uint32_t aoff = (uint32_t)(wm * 64 + lrow) * ROWB + lcol;
    const uint32_t boff = (uint32_t)(wn * 64 + lrow) * ROWB + lcol;

    float acc[4][8][4];                   // 128 regs: 64 rows x 64 cols / warp
    #pragma unroll
    for (int i = 0; i < 4; i++)
        #pragma unroll
        for (int j = 0; j < 8; j++)
            #pragma unroll
            for (int q = 0; q < 4; q++) acc[i][j][q] = 0.0f;

    // prologue: stage 0
    load_stage(sbase, 0, aRow0, nCol0, tid);
    CP_COMMIT();

    for (int t = 0; t < NITK; t++) {
        CP_WAIT0();            // own cp.async for stage t complete
        __syncthreads();       // data visible; prev compute done (buffer free)

        if (t + 1 < NITK) {    // prefetch overlaps the whole compute below
            load_stage(sbase + ((t + 1) & 1) * ST_SIZE, (t + 1) * KC,
                       aRow0, nCol0, tid);
            CP_COMMIT();
        }

        const uint32_t st = sbase + (t & 1) * ST_SIZE;

        #pragma unroll
        for (int kk = 0; kk < 4; kk++) {   // four k16 steps per chunk
            const uint32_t kb = (uint32_t)(kk * 32);
            uint32_t bh[4][4];
            #pragma unroll
            for (int g = 0; g < 4; g++) {  // 4 n16 groups (64 cols)
                uint32_t bd = st + boff + (uint32_t)(g * 16) * ROWB + kb;
                ldsm_x4(bh[g][0], bh[g][1], bh[g][2], bh[g][3], bd + OFF_BH);
            }
            #pragma unroll
            for (int mt = 0; mt < 4; mt++) {
                const uint32_t ad = st + aoff + (uint32_t)(mt * 16) * ROWB + kb;
                uint32_t af[4];
                ldsm_x4(af[0], af[1], af[2], af[3], ad + OFF_AH);
                #pragma unroll
                for (int nt = 0; nt < 8; nt++) {
                    const int g = nt >> 1, o = nt & 1;
                    mma_f16(acc[mt][nt], af, bh[g][0 + o], bh[g][2 + o]);
                }
            }
        }
    }

    // epilogue: undo the x8192 A pre-scale (exact), c fragment -> gmem.
    const float inv = 1.0f / 8192.0f;
    const int r0 = aRow0 + wm * 64 + (lane >> 2);
    const int c0 = nCol0 + wn * 64 + (lane & 3) * 2;
    #pragma unroll
    for (int mt = 0; mt < 4; mt++) {
        #pragma unroll
        for (int nt = 0; nt < 8; nt++) {
            const int rr = r0 + mt * 16;
            const int cc = c0 + nt * 8;
            *(float2*)(out + (size_t)rr * M_COLS + cc) =
                make_float2(acc[mt][nt][0] * inv, acc[mt][nt][1] * inv);
            *(float2*)(out + (size_t)(rr + 8) * M_COLS + cc) =
                make_float2(acc[mt][nt][2] * inv, acc[mt][nt][3] * inv);
        }
    }
}

// ---------------------------------------------------------------------------
// kernel_launch: M (f32, 8192*4096), D (f32, 8192), P (i32, 1024) ->
// out f32 [1024, 4096]. Graph-capturable: 3 kernel launches, no sync/alloc.
// ---------------------------------------------------------------------------
extern "C" void kernel_launch(void* const* d_in, const int* in_sizes, int n_in,
                              void* d_out, int out_size) {
    const float* Mmat = (const float*)d_in[0];
    const float* D    = (const float*)d_in[1];
    const int*   P    = (const int*)  d_in[2];
    float*       out  = (float*)d_out;

    // Kernel 1: build A' (fp16, pre-scaled by 8192)
    {
        const int total = D_SKETCH * N_DIM / 2;
        build_A_kernel<<<total / 256, 256>>>(D, P);
    }
    // Kernel 2: transpose M -> fp16 [N,K]
    {
        dim3 grid(M_COLS / 32, N_DIM / 64);   // 128 x 128
        dim3 blk(32, 8);
        conv_B_kernel<<<grid, blk>>>(Mmat);
    }
    // Kernel 3: tensor-core (mma.sync fp16) GEMM, 128 CTAs = one full wave.
    {
        cudaFuncSetAttribute(gemm_mma_kernel,
                             cudaFuncAttributeMaxDynamicSharedMemorySize, SMEM_TOTAL);
        dim3 grid(D_SKETCH / BM, M_COLS / BN);   // 8 x 16 = 128 CTAs
        gemm_mma_kernel<<<grid, 256, SMEM_TOTAL>>>(out);
    }
}